// round 7
// baseline (speedup 1.0000x reference)
#include <cuda_runtime.h>
#include <cstdint>
#include <cstddef>

// Problem constants
#define NN   4096
#define INF_ 128
#define DD   256
#define HH   8
#define HDIM 32
#define LL   2
#define EE   131072
#define PP   200000

// ---------------- scratch (device globals; no allocation allowed) ----------------
__device__ float g_h[NN * DD];
__device__ float g_hproj[NN * DD];
__device__ float g_qkv[NN * 3 * DD];
__device__ float g_attn[NN * DD];
__device__ float g_attnout[NN * DD];
__device__ float g_tmp[NN * DD];
__device__ float g_ws[NN];
__device__ float g_projT[INF_ * DD];          // 128 x 256
__device__ float g_inT[LL * DD * 3 * DD];     // per layer: 256 x 768
__device__ float g_outT[LL * DD * DD];        // 256 x 256
__device__ float g_ffT[LL * DD * DD];         // 256 x 256
__device__ float g_pw1T[DD * (DD / 2)];       // 256 x 128

// ---------------- transpose: dst[C x R] = src[R x C]^T ----------------
__global__ void transpose_kernel(float* __restrict__ dst, const float* __restrict__ src,
                                 int R, int C) {
    __shared__ float t[32][33];
    int bx = blockIdx.x * 32, by = blockIdx.y * 32;
    int x = bx + threadIdx.x;   // col in src
    int y = by + threadIdx.y;   // row in src
    if (x < C && y < R) t[threadIdx.y][threadIdx.x] = src[(size_t)y * C + x];
    __syncthreads();
    int ox = by + threadIdx.x;  // col in dst (= row in src)
    int oy = bx + threadIdx.y;  // row in dst (= col in src)
    if (ox < R && oy < C) dst[(size_t)oy * R + ox] = t[threadIdx.x][threadIdx.y];
}

// ---------------- GEMM: C[M x Nc] = A[M x K] @ B[K x Nc] + bias ----------------
// M % 64 == 0, Nc % 64 == 0, K % 16 == 0. 256 threads, 64x64 tile, 4x4 micro-tile.
__global__ __launch_bounds__(256) void gemm_bias(const float* __restrict__ A,
                                                 const float* __restrict__ B,
                                                 const float* __restrict__ bias,
                                                 float* __restrict__ C,
                                                 int M, int Nc, int K) {
    __shared__ float As[64][17];
    __shared__ float Bs[16][64];
    int tid = threadIdx.x;
    int tx = tid & 15, ty = tid >> 4;
    int m0 = blockIdx.y * 64, n0 = blockIdx.x * 64;

    float acc[4][4];
#pragma unroll
    for (int i = 0; i < 4; i++)
#pragma unroll
        for (int j = 0; j < 4; j++) acc[i][j] = 0.f;

    for (int k0 = 0; k0 < K; k0 += 16) {
        // A tile 64x16 (float4 per thread)
        {
            int r = tid >> 2;
            int c4 = (tid & 3) * 4;
            const float4 v = *(const float4*)(A + (size_t)(m0 + r) * K + k0 + c4);
            As[r][c4] = v.x; As[r][c4 + 1] = v.y; As[r][c4 + 2] = v.z; As[r][c4 + 3] = v.w;
        }
        // B tile 16x64
#pragma unroll
        for (int j = 0; j < 4; j++) {
            int idx = tid + j * 256;
            int r = idx >> 6, c = idx & 63;
            Bs[r][c] = B[(size_t)(k0 + r) * Nc + n0 + c];
        }
        __syncthreads();
#pragma unroll
        for (int k = 0; k < 16; k++) {
            float a0 = As[ty * 4 + 0][k], a1 = As[ty * 4 + 1][k];
            float a2 = As[ty * 4 + 2][k], a3 = As[ty * 4 + 3][k];
            float4 b = *(const float4*)&Bs[k][tx * 4];
            acc[0][0] += a0 * b.x; acc[0][1] += a0 * b.y; acc[0][2] += a0 * b.z; acc[0][3] += a0 * b.w;
            acc[1][0] += a1 * b.x; acc[1][1] += a1 * b.y; acc[1][2] += a1 * b.z; acc[1][3] += a1 * b.w;
            acc[2][0] += a2 * b.x; acc[2][1] += a2 * b.y; acc[2][2] += a2 * b.z; acc[2][3] += a2 * b.w;
            acc[3][0] += a3 * b.x; acc[3][1] += a3 * b.y; acc[3][2] += a3 * b.z; acc[3][3] += a3 * b.w;
        }
        __syncthreads();
    }
#pragma unroll
    for (int i = 0; i < 4; i++) {
        int row = m0 + ty * 4 + i;
#pragma unroll
        for (int j = 0; j < 4; j++) {
            int col = n0 + tx * 4 + j;
            C[(size_t)row * Nc + col] = acc[i][j] + bias[col];
        }
    }
}

// ---------------- Flash attention (fp32, HD=32, full dense softmax) ----------------
// grid: (NN/64, HH). qkv row layout: [q(256) | k(256) | v(256)], head h at cols h*32.
// Output attn: (N, D) with column h*32+d.
__global__ __launch_bounds__(256) void flash_kernel(const float* __restrict__ qkv,
                                                    float* __restrict__ attn) {
    __shared__ float Qs[64][33];
    __shared__ float Ks[64][33];
    __shared__ float Vs[64][33];
    __shared__ float Ps[64][65];

    int tid = threadIdx.x;
    int tx = tid & 15, ty = tid >> 4;
    int qt = blockIdx.x, hh = blockIdx.y;

    const float scale = 0.17677669529663687f;  // 1/sqrt(32)
    const float* qb = qkv + (size_t)qt * 64 * 768 + hh * 32;
    for (int idx = tid; idx < 2048; idx += 256) {
        int r = idx >> 5, c = idx & 31;
        Qs[r][c] = qb[(size_t)r * 768 + c] * scale;
    }

    float o[4][2];
    float m_run[4], l_run[4];
#pragma unroll
    for (int i = 0; i < 4; i++) { m_run[i] = -3.0e38f; l_run[i] = 0.f; o[i][0] = 0.f; o[i][1] = 0.f; }

    for (int kt = 0; kt < NN / 64; kt++) {
        __syncthreads();   // prev iteration's PV reads done before overwriting Ks/Vs/Ps
        const float* kb = qkv + (size_t)kt * 64 * 768 + 256 + hh * 32;
        const float* vb = kb + 256;
        for (int idx = tid; idx < 2048; idx += 256) {
            int r = idx >> 5, c = idx & 31;
            Ks[r][c] = kb[(size_t)r * 768 + c];
            Vs[r][c] = vb[(size_t)r * 768 + c];
        }
        __syncthreads();

        float s[4][4];
#pragma unroll
        for (int i = 0; i < 4; i++)
#pragma unroll
            for (int j = 0; j < 4; j++) s[i][j] = 0.f;
#pragma unroll 8
        for (int d = 0; d < 32; d++) {
            float a0 = Qs[ty * 4 + 0][d], a1 = Qs[ty * 4 + 1][d];
            float a2 = Qs[ty * 4 + 2][d], a3 = Qs[ty * 4 + 3][d];
            float b0 = Ks[tx * 4 + 0][d], b1 = Ks[tx * 4 + 1][d];
            float b2 = Ks[tx * 4 + 2][d], b3 = Ks[tx * 4 + 3][d];
            s[0][0] += a0 * b0; s[0][1] += a0 * b1; s[0][2] += a0 * b2; s[0][3] += a0 * b3;
            s[1][0] += a1 * b0; s[1][1] += a1 * b1; s[1][2] += a1 * b2; s[1][3] += a1 * b3;
            s[2][0] += a2 * b0; s[2][1] += a2 * b1; s[2][2] += a2 * b2; s[2][3] += a2 * b3;
            s[3][0] += a3 * b0; s[3][1] += a3 * b1; s[3][2] += a3 * b2; s[3][3] += a3 * b3;
        }
        // online softmax: stats replicated identically across the 16 lanes of each row group
#pragma unroll
        for (int i = 0; i < 4; i++) {
            float mx = fmaxf(fmaxf(s[i][0], s[i][1]), fmaxf(s[i][2], s[i][3]));
#pragma unroll
            for (int off = 8; off; off >>= 1)
                mx = fmaxf(mx, __shfl_xor_sync(0xffffffffu, mx, off, 16));
            float m_new = fmaxf(m_run[i], mx);
            float alpha = __expf(m_run[i] - m_new);
            float sum = 0.f;
#pragma unroll
            for (int j = 0; j < 4; j++) {
                float p = __expf(s[i][j] - m_new);
                Ps[ty * 4 + i][tx * 4 + j] = p;
                sum += p;
            }
#pragma unroll
            for (int off = 8; off; off >>= 1)
                sum += __shfl_xor_sync(0xffffffffu, sum, off, 16);
            l_run[i] = l_run[i] * alpha + sum;
            m_run[i] = m_new;
            o[i][0] *= alpha; o[i][1] *= alpha;
        }
        __syncthreads();
        // O += P @ V
#pragma unroll 4
        for (int kk = 0; kk < 64; kk++) {
            float p0 = Ps[ty * 4 + 0][kk], p1 = Ps[ty * 4 + 1][kk];
            float p2 = Ps[ty * 4 + 2][kk], p3 = Ps[ty * 4 + 3][kk];
            float v0 = Vs[kk][tx * 2 + 0], v1 = Vs[kk][tx * 2 + 1];
            o[0][0] += p0 * v0; o[0][1] += p0 * v1;
            o[1][0] += p1 * v0; o[1][1] += p1 * v1;
            o[2][0] += p2 * v0; o[2][1] += p2 * v1;
            o[3][0] += p3 * v0; o[3][1] += p3 * v1;
        }
    }
#pragma unroll
    for (int i = 0; i < 4; i++) {
        float inv = 1.f / l_run[i];
        int row = qt * 64 + ty * 4 + i;
        attn[(size_t)row * DD + hh * 32 + tx * 2 + 0] = o[i][0] * inv;
        attn[(size_t)row * DD + hh * 32 + tx * 2 + 1] = o[i][1] * inv;
    }
}

// ---------------- LayerNorm helpers ----------------
__device__ __forceinline__ float block_sum256(float v) {
    __shared__ float sh[8];
    int lane = threadIdx.x & 31, w = threadIdx.x >> 5;
#pragma unroll
    for (int off = 16; off; off >>= 1) v += __shfl_xor_sync(0xffffffffu, v, off);
    __syncthreads();  // protect sh across repeated calls
    if (lane == 0) sh[w] = v;
    __syncthreads();
    if (threadIdx.x < 32) {
        float t = (lane < 8) ? sh[lane] : 0.f;
#pragma unroll
        for (int off = 4; off; off >>= 1) t += __shfl_xor_sync(0xffffffffu, t, off);
        if (lane == 0) sh[0] = t;
    }
    __syncthreads();
    return sh[0];
}

// h[row] = LN(h[row] + add[row] * (ws ? ws[row] : 1)) * g + b
__global__ __launch_bounds__(256) void ln_kernel(float* __restrict__ h,
                                                 const float* __restrict__ add,
                                                 const float* __restrict__ ws,
                                                 const float* __restrict__ g,
                                                 const float* __restrict__ b) {
    int row = blockIdx.x, c = threadIdx.x;
    float w = ws ? ws[row] : 1.f;
    float v = h[(size_t)row * DD + c] + add[(size_t)row * DD + c] * w;
    float mean = block_sum256(v) * (1.f / 256.f);
    float d = v - mean;
    float var = block_sum256(d * d) * (1.f / 256.f);
    h[(size_t)row * DD + c] = d * rsqrtf(var + 1e-5f) * g[c] + b[c];
}

// ---------------- small elementwise / scatter kernels ----------------
__global__ void zero_kernel(float* p) { p[blockIdx.x * 256 + threadIdx.x] = 0.f; }

__global__ void scatter_kernel(const float* __restrict__ ew, const int* __restrict__ src,
                               float* __restrict__ ws, int E) {
    int i = blockIdx.x * 256 + threadIdx.x;
    if (i < E) atomicAdd(&ws[src[i]], ew[i]);
}

__global__ void copy_kernel(float* __restrict__ dst, const float* __restrict__ s) {
    int i = blockIdx.x * 256 + threadIdx.x;
    dst[i] = s[i];
}

__global__ void add2_kernel(float* __restrict__ dst, const float* __restrict__ a,
                            const float* __restrict__ b) {
    int i = blockIdx.x * 256 + threadIdx.x;
    dst[i] = a[i] + b[i];
}

// ---------------- fused link predictor ----------------
// For pair p (0..2P-1): z = hc[s]*hc[d] (256); hid = z @ pw1^T + pb1 (128);
// score = leaky(hid,0.2) . pw2 + pb2.  128 pairs/block, 8x8 micro-tile GEMM, K chunks of 32.
__global__ __launch_bounds__(256) void predict_kernel(const float* __restrict__ hc,
                                                      const int* __restrict__ ps,
                                                      const int* __restrict__ pd,
                                                      const int* __restrict__ ns,
                                                      const int* __restrict__ nd,
                                                      const float* __restrict__ w1t,  // 256x128
                                                      const float* __restrict__ pb1,
                                                      const float* __restrict__ pw2,
                                                      const float* __restrict__ pb2,
                                                      float* __restrict__ out, int P) {
    __shared__ float Zs[128][34];
    __shared__ float Ws[32][128];
    __shared__ int sidx[128], didx[128];

    int tid = threadIdx.x;
    int p0 = blockIdx.x * 128;
    if (tid < 128) {
        int p = p0 + tid;
        int s, d;
        if (p < P) { s = ps[p]; d = pd[p]; }
        else       { s = ns[p - P]; d = nd[p - P]; }
        sidx[tid] = s; didx[tid] = d;
    }
    __syncthreads();

    int tx = tid & 15, ty = tid >> 4;
    float acc[8][8];
#pragma unroll
    for (int i = 0; i < 8; i++)
#pragma unroll
        for (int j = 0; j < 8; j++) acc[i][j] = 0.f;

    int lane16 = tid & 15, grp = tid >> 4;

    for (int k0 = 0; k0 < 256; k0 += 32) {
        // build Z chunk on the fly (hc is L2-resident: 4 MB)
#pragma unroll
        for (int pp = 0; pp < 8; pp++) {
            int p = grp * 8 + pp;
            const float* sr = hc + (size_t)sidx[p] * DD + k0;
            const float* dr = hc + (size_t)didx[p] * DD + k0;
            Zs[p][lane16]      = sr[lane16]      * dr[lane16];
            Zs[p][lane16 + 16] = sr[lane16 + 16] * dr[lane16 + 16];
        }
        // W chunk 32x128
#pragma unroll
        for (int j = 0; j < 16; j++) {
            int idx = tid + j * 256;
            int k = idx >> 7, n = idx & 127;
            Ws[k][n] = w1t[(size_t)(k0 + k) * 128 + n];
        }
        __syncthreads();
#pragma unroll 4
        for (int k = 0; k < 32; k++) {
            float a[8];
#pragma unroll
            for (int i = 0; i < 8; i++) a[i] = Zs[ty * 8 + i][k];
            float4 b0 = *(const float4*)&Ws[k][tx * 8];
            float4 b1 = *(const float4*)&Ws[k][tx * 8 + 4];
            float bb[8] = {b0.x, b0.y, b0.z, b0.w, b1.x, b1.y, b1.z, b1.w};
#pragma unroll
            for (int i = 0; i < 8; i++)
#pragma unroll
                for (int j = 0; j < 8; j++) acc[i][j] += a[i] * bb[j];
        }
        __syncthreads();
    }

    float pb2v = pb2[0];
#pragma unroll
    for (int i = 0; i < 8; i++) {
        float sum = 0.f;
#pragma unroll
        for (int j = 0; j < 8; j++) {
            int n = tx * 8 + j;
            float hv = acc[i][j] + pb1[n];
            hv = (hv > 0.f) ? hv : 0.2f * hv;
            sum += hv * pw2[n];
        }
#pragma unroll
        for (int off = 8; off; off >>= 1)
            sum += __shfl_xor_sync(0xffffffffu, sum, off, 16);
        if (tx == 0) out[p0 + ty * 8 + i] = sum + pb2v;
    }
}

// ---------------- launch ----------------
extern "C" void kernel_launch(void* const* d_in, const int* in_sizes, int n_in,
                              void* d_out, int out_size) {
    (void)in_sizes; (void)n_in; (void)out_size;
    const float* x       = (const float*)d_in[0];
    const float* edge_w  = (const float*)d_in[1];
    const int*   src     = (const int*)d_in[2];
    /* d_in[3] = dst (unused: segment-sum is over src) */
    const int* pos_src = (const int*)d_in[4];
    const int* pos_dst = (const int*)d_in[5];
    const int* neg_src = (const int*)d_in[6];
    const int* neg_dst = (const int*)d_in[7];
    const float* proj_w = (const float*)d_in[8];
    const float* proj_b = (const float*)d_in[9];
    const float* in_w   = (const float*)d_in[10];
    const float* in_b   = (const float*)d_in[11];
    const float* out_w  = (const float*)d_in[12];
    const float* out_b  = (const float*)d_in[13];
    const float* ff_w   = (const float*)d_in[14];
    const float* ff_b   = (const float*)d_in[15];
    const float* g1     = (const float*)d_in[16];
    const float* b1     = (const float*)d_in[17];
    const float* g2     = (const float*)d_in[18];
    const float* b2     = (const float*)d_in[19];
    const float* pw1    = (const float*)d_in[20];
    const float* pb1    = (const float*)d_in[21];
    const float* pw2    = (const float*)d_in[22];
    const float* pb2    = (const float*)d_in[23];

    float* out = (float*)d_out;
    float* out_hc = out + 2 * PP;   // [pos(P) | neg(P) | h_combined(N*D)]

    float *h, *hproj, *qkv, *attn, *attnout, *tmp, *ws;
    float *projT, *inT, *outT, *ffT, *pw1T;
    cudaGetSymbolAddress((void**)&h, g_h);
    cudaGetSymbolAddress((void**)&hproj, g_hproj);
    cudaGetSymbolAddress((void**)&qkv, g_qkv);
    cudaGetSymbolAddress((void**)&attn, g_attn);
    cudaGetSymbolAddress((void**)&attnout, g_attnout);
    cudaGetSymbolAddress((void**)&tmp, g_tmp);
    cudaGetSymbolAddress((void**)&ws, g_ws);
    cudaGetSymbolAddress((void**)&projT, g_projT);
    cudaGetSymbolAddress((void**)&inT, g_inT);
    cudaGetSymbolAddress((void**)&outT, g_outT);
    cudaGetSymbolAddress((void**)&ffT, g_ffT);
    cudaGetSymbolAddress((void**)&pw1T, g_pw1T);

    dim3 tb(32, 32);
    // weight pre-transposes (coalesced GEMM B operands)
    transpose_kernel<<<dim3(4, 8),  tb>>>(projT, proj_w, 256, 128);   // -> 128x256
    transpose_kernel<<<dim3(8, 4),  tb>>>(pw1T, pw1, 128, 256);       // -> 256x128
    for (int l = 0; l < LL; l++) {
        transpose_kernel<<<dim3(8, 24), tb>>>(inT + l * 256 * 768, in_w + l * 768 * 256, 768, 256);
        transpose_kernel<<<dim3(8, 8),  tb>>>(outT + l * 256 * 256, out_w + l * 256 * 256, 256, 256);
        transpose_kernel<<<dim3(8, 8),  tb>>>(ffT + l * 256 * 256, ff_w + l * 256 * 256, 256, 256);
    }

    // h_proj = x @ proj_w^T + proj_b ; h = h_proj
    gemm_bias<<<dim3(4, 64), 256>>>(x, projT, proj_b, hproj, NN, DD, INF_);
    copy_kernel<<<NN * DD / 256, 256>>>(h, hproj);

    for (int l = 0; l < LL; l++) {
        gemm_bias<<<dim3(12, 64), 256>>>(h, inT + l * 256 * 768, in_b + l * 768, qkv, NN, 3 * DD, DD);
        flash_kernel<<<dim3(NN / 64, HH), 256>>>(qkv, attn);
        gemm_bias<<<dim3(4, 64), 256>>>(attn, outT + l * 256 * 256, out_b + l * DD, attnout, NN, DD, DD);
        zero_kernel<<<NN / 256, 256>>>(ws);
        scatter_kernel<<<EE / 256, 256>>>(edge_w + (size_t)l * EE, src + (size_t)l * EE, ws, EE);
        ln_kernel<<<NN, 256>>>(h, attnout, ws, g1 + l * DD, b1 + l * DD);
        gemm_bias<<<dim3(4, 64), 256>>>(h, ffT + l * 256 * 256, ff_b + l * DD, tmp, NN, DD, DD);
        ln_kernel<<<NN, 256>>>(h, tmp, nullptr, g2 + l * DD, b2 + l * DD);
    }

    add2_kernel<<<NN * DD / 256, 256>>>(out_hc, h, hproj);
    predict_kernel<<<(2 * PP) / 128, 256>>>(out_hc, pos_src, pos_dst, neg_src, neg_dst,
                                            pw1T, pb1, pw2, pb2, out, PP);
}

// round 8
// speedup vs baseline: 1.0118x; 1.0118x over previous
#include <cuda_runtime.h>
#include <cstdint>
#include <cstddef>

// Problem constants
#define NN   4096
#define INF_ 128
#define DD   256
#define HH   8
#define HDIM 32
#define LL   2
#define EE   131072
#define PP   200000

// ---------------- packed f32x2 helpers (SASS FFMA2 — PTX-only pattern) ----------------
__device__ __forceinline__ unsigned long long pk2(float x, float y) {
    unsigned long long r;
    asm("mov.b64 %0, {%1, %2};" : "=l"(r) : "f"(x), "f"(y));
    return r;
}
__device__ __forceinline__ unsigned long long dup2(float x) { return pk2(x, x); }
__device__ __forceinline__ void fma2(unsigned long long& d, unsigned long long a,
                                     unsigned long long b) {
    asm("fma.rn.f32x2 %0, %1, %2, %0;" : "+l"(d) : "l"(a), "l"(b));
}
__device__ __forceinline__ unsigned long long mul2(unsigned long long a, unsigned long long b) {
    unsigned long long r;
    asm("mul.rn.f32x2 %0, %1, %2;" : "=l"(r) : "l"(a), "l"(b));
    return r;
}
__device__ __forceinline__ void upk2(unsigned long long v, float& x, float& y) {
    asm("mov.b64 {%0, %1}, %2;" : "=f"(x), "=f"(y) : "l"(v));
}

// ---------------- scratch (device globals; no allocation allowed) ----------------
__device__ float g_h[NN * DD];
__device__ float g_hproj[NN * DD];
__device__ float g_qkv[NN * 3 * DD];
__device__ float g_attn[NN * DD];
__device__ float g_attnout[NN * DD];
__device__ float g_tmp[NN * DD];
__device__ float g_ws[NN];
__device__ float g_projT[INF_ * DD];          // 128 x 256
__device__ float g_inT[LL * DD * 3 * DD];     // per layer: 256 x 768
__device__ float g_outT[LL * DD * DD];        // 256 x 256
__device__ float g_ffT[LL * DD * DD];         // 256 x 256
__device__ float g_pw1T[DD * (DD / 2)];       // 256 x 128

// ---------------- transpose: dst[C x R] = src[R x C]^T ----------------
__global__ void transpose_kernel(float* __restrict__ dst, const float* __restrict__ src,
                                 int R, int C) {
    __shared__ float t[32][33];
    int bx = blockIdx.x * 32, by = blockIdx.y * 32;
    int x = bx + threadIdx.x;
    int y = by + threadIdx.y;
    if (x < C && y < R) t[threadIdx.y][threadIdx.x] = src[(size_t)y * C + x];
    __syncthreads();
    int ox = by + threadIdx.x;
    int oy = bx + threadIdx.y;
    if (ox < R && oy < C) dst[(size_t)oy * R + ox] = t[threadIdx.x][threadIdx.y];
}

// ---------------- GEMM: C[M x Nc] = A[M x K] @ B[K x Nc] + bias ----------------
// 256 threads, 64x64 tile, 4x4 micro-tile, packed f32x2 accumulators.
__global__ __launch_bounds__(256) void gemm_bias(const float* __restrict__ A,
                                                 const float* __restrict__ B,
                                                 const float* __restrict__ bias,
                                                 float* __restrict__ C,
                                                 int M, int Nc, int K) {
    __shared__ float As[64][17];
    __shared__ float Bs[16][64];
    int tid = threadIdx.x;
    int tx = tid & 15, ty = tid >> 4;
    int m0 = blockIdx.y * 64, n0 = blockIdx.x * 64;

    unsigned long long acc2[4][2];
#pragma unroll
    for (int i = 0; i < 4; i++) { acc2[i][0] = 0ull; acc2[i][1] = 0ull; }

    for (int k0 = 0; k0 < K; k0 += 16) {
        {
            int r = tid >> 2;
            int c4 = (tid & 3) * 4;
            const float4 v = *(const float4*)(A + (size_t)(m0 + r) * K + k0 + c4);
            As[r][c4] = v.x; As[r][c4 + 1] = v.y; As[r][c4 + 2] = v.z; As[r][c4 + 3] = v.w;
        }
#pragma unroll
        for (int j = 0; j < 4; j++) {
            int idx = tid + j * 256;
            int r = idx >> 6, c = idx & 63;
            Bs[r][c] = B[(size_t)(k0 + r) * Nc + n0 + c];
        }
        __syncthreads();
#pragma unroll
        for (int k = 0; k < 16; k++) {
            ulonglong2 b = *(const ulonglong2*)&Bs[k][tx * 4];
#pragma unroll
            for (int i = 0; i < 4; i++) {
                unsigned long long ad = dup2(As[ty * 4 + i][k]);
                fma2(acc2[i][0], ad, b.x);
                fma2(acc2[i][1], ad, b.y);
            }
        }
        __syncthreads();
    }
#pragma unroll
    for (int i = 0; i < 4; i++) {
        int row = m0 + ty * 4 + i;
        float c0, c1, c2, c3;
        upk2(acc2[i][0], c0, c1);
        upk2(acc2[i][1], c2, c3);
        int col = n0 + tx * 4;
        C[(size_t)row * Nc + col + 0] = c0 + bias[col + 0];
        C[(size_t)row * Nc + col + 1] = c1 + bias[col + 1];
        C[(size_t)row * Nc + col + 2] = c2 + bias[col + 2];
        C[(size_t)row * Nc + col + 3] = c3 + bias[col + 3];
    }
}

// ---------------- Flash attention (fp32, HD=32, full dense softmax) ----------------
// grid: (NN/64, HH). Transposed Q/K smem -> vector LDS; packed FFMA2 math.
__global__ __launch_bounds__(256) void flash_kernel(const float* __restrict__ qkv,
                                                    float* __restrict__ attn) {
    __shared__ float Qt[32][68];   // Qt[d][row] (scaled)
    __shared__ float Kt[32][68];   // Kt[d][row]
    __shared__ float Vs[64][34];   // Vs[row][d]
    __shared__ float Ps[64][68];   // Ps[row][kk]

    int tid = threadIdx.x;
    int tx = tid & 15, ty = tid >> 4;
    int qt = blockIdx.x, hh = blockIdx.y;

    const float scale = 0.17677669529663687f;  // 1/sqrt(32)
    const float* qb = qkv + (size_t)qt * 64 * 768 + hh * 32;
    for (int idx = tid; idx < 2048; idx += 256) {
        int r = idx >> 5, c = idx & 31;
        Qt[c][r] = qb[(size_t)r * 768 + c] * scale;
    }

    unsigned long long o2[4];
    float m_run[4], l_run[4];
#pragma unroll
    for (int i = 0; i < 4; i++) { m_run[i] = -3.0e38f; l_run[i] = 0.f; o2[i] = 0ull; }

    for (int kt = 0; kt < NN / 64; kt++) {
        __syncthreads();   // previous iteration's reads of Kt/Vs/Ps complete
        const float* kb = qkv + (size_t)kt * 64 * 768 + 256 + hh * 32;
        const float* vb = kb + 256;
        for (int idx = tid; idx < 2048; idx += 256) {
            int r = idx >> 5, c = idx & 31;
            Kt[c][r] = kb[(size_t)r * 768 + c];
            Vs[r][c] = vb[(size_t)r * 768 + c];
        }
        __syncthreads();

        // S = Q @ K^T : 4x4 micro-tile, packed columns
        unsigned long long s2[4][2];
#pragma unroll
        for (int i = 0; i < 4; i++) { s2[i][0] = 0ull; s2[i][1] = 0ull; }
#pragma unroll 8
        for (int d = 0; d < 32; d++) {
            float4 aq = *(const float4*)&Qt[d][ty * 4];
            ulonglong2 bk = *(const ulonglong2*)&Kt[d][tx * 4];
            unsigned long long a0 = dup2(aq.x), a1 = dup2(aq.y);
            unsigned long long a2 = dup2(aq.z), a3 = dup2(aq.w);
            fma2(s2[0][0], a0, bk.x); fma2(s2[0][1], a0, bk.y);
            fma2(s2[1][0], a1, bk.x); fma2(s2[1][1], a1, bk.y);
            fma2(s2[2][0], a2, bk.x); fma2(s2[2][1], a2, bk.y);
            fma2(s2[3][0], a3, bk.x); fma2(s2[3][1], a3, bk.y);
        }

        // online softmax (stats replicated across the 16 lanes of each row group)
#pragma unroll
        for (int i = 0; i < 4; i++) {
            float sj[4];
            upk2(s2[i][0], sj[0], sj[1]);
            upk2(s2[i][1], sj[2], sj[3]);
            float mx = fmaxf(fmaxf(sj[0], sj[1]), fmaxf(sj[2], sj[3]));
#pragma unroll
            for (int off = 8; off; off >>= 1)
                mx = fmaxf(mx, __shfl_xor_sync(0xffffffffu, mx, off, 16));
            float m_new = fmaxf(m_run[i], mx);
            float alpha = __expf(m_run[i] - m_new);
            float4 pv;
            pv.x = __expf(sj[0] - m_new);
            pv.y = __expf(sj[1] - m_new);
            pv.z = __expf(sj[2] - m_new);
            pv.w = __expf(sj[3] - m_new);
            *(float4*)&Ps[ty * 4 + i][tx * 4] = pv;
            float sum = pv.x + pv.y + pv.z + pv.w;
#pragma unroll
            for (int off = 8; off; off >>= 1)
                sum += __shfl_xor_sync(0xffffffffu, sum, off, 16);
            l_run[i] = l_run[i] * alpha + sum;
            m_run[i] = m_new;
            o2[i] = mul2(o2[i], dup2(alpha));
        }
        __syncthreads();

        // O += P @ V : vector loads of P rows, packed V columns
#pragma unroll 4
        for (int kk0 = 0; kk0 < 16; kk0++) {
            float pr[4][4];
#pragma unroll
            for (int i = 0; i < 4; i++) {
                float4 t = *(const float4*)&Ps[ty * 4 + i][kk0 * 4];
                pr[i][0] = t.x; pr[i][1] = t.y; pr[i][2] = t.z; pr[i][3] = t.w;
            }
#pragma unroll
            for (int q = 0; q < 4; q++) {
                int kk = kk0 * 4 + q;
                unsigned long long v = *(const unsigned long long*)&Vs[kk][tx * 2];
                fma2(o2[0], dup2(pr[0][q]), v);
                fma2(o2[1], dup2(pr[1][q]), v);
                fma2(o2[2], dup2(pr[2][q]), v);
                fma2(o2[3], dup2(pr[3][q]), v);
            }
        }
    }
#pragma unroll
    for (int i = 0; i < 4; i++) {
        float inv = 1.f / l_run[i];
        float x, y;
        upk2(o2[i], x, y);
        int row = qt * 64 + ty * 4 + i;
        attn[(size_t)row * DD + hh * 32 + tx * 2 + 0] = x * inv;
        attn[(size_t)row * DD + hh * 32 + tx * 2 + 1] = y * inv;
    }
}

// ---------------- LayerNorm helpers ----------------
__device__ __forceinline__ float block_sum256(float v) {
    __shared__ float sh[8];
    int lane = threadIdx.x & 31, w = threadIdx.x >> 5;
#pragma unroll
    for (int off = 16; off; off >>= 1) v += __shfl_xor_sync(0xffffffffu, v, off);
    __syncthreads();
    if (lane == 0) sh[w] = v;
    __syncthreads();
    if (threadIdx.x < 32) {
        float t = (lane < 8) ? sh[lane] : 0.f;
#pragma unroll
        for (int off = 4; off; off >>= 1) t += __shfl_xor_sync(0xffffffffu, t, off);
        if (lane == 0) sh[0] = t;
    }
    __syncthreads();
    return sh[0];
}

__global__ __launch_bounds__(256) void ln_kernel(float* __restrict__ h,
                                                 const float* __restrict__ add,
                                                 const float* __restrict__ ws,
                                                 const float* __restrict__ g,
                                                 const float* __restrict__ b) {
    int row = blockIdx.x, c = threadIdx.x;
    float w = ws ? ws[row] : 1.f;
    float v = h[(size_t)row * DD + c] + add[(size_t)row * DD + c] * w;
    float mean = block_sum256(v) * (1.f / 256.f);
    float d = v - mean;
    float var = block_sum256(d * d) * (1.f / 256.f);
    h[(size_t)row * DD + c] = d * rsqrtf(var + 1e-5f) * g[c] + b[c];
}

// ---------------- small elementwise / scatter kernels ----------------
__global__ void zero_kernel(float* p) { p[blockIdx.x * 256 + threadIdx.x] = 0.f; }

__global__ void scatter_kernel(const float* __restrict__ ew, const int* __restrict__ src,
                               float* __restrict__ ws, int E) {
    int i = blockIdx.x * 256 + threadIdx.x;
    if (i < E) atomicAdd(&ws[src[i]], ew[i]);
}

__global__ void copy_kernel(float* __restrict__ dst, const float* __restrict__ s) {
    int i = blockIdx.x * 256 + threadIdx.x;
    dst[i] = s[i];
}

__global__ void add2_kernel(float* __restrict__ dst, const float* __restrict__ a,
                            const float* __restrict__ b) {
    int i = blockIdx.x * 256 + threadIdx.x;
    dst[i] = a[i] + b[i];
}

// ---------------- fused link predictor (packed f32x2) ----------------
__global__ __launch_bounds__(256) void predict_kernel(const float* __restrict__ hc,
                                                      const int* __restrict__ ps,
                                                      const int* __restrict__ pd,
                                                      const int* __restrict__ ns,
                                                      const int* __restrict__ nd,
                                                      const float* __restrict__ w1t,  // 256x128
                                                      const float* __restrict__ pb1,
                                                      const float* __restrict__ pw2,
                                                      const float* __restrict__ pb2,
                                                      float* __restrict__ out, int P) {
    __shared__ float Zs[128][34];
    __shared__ float Ws[32][128];
    __shared__ int sidx[128], didx[128];

    int tid = threadIdx.x;
    int p0 = blockIdx.x * 128;
    if (tid < 128) {
        int p = p0 + tid;
        int s, d;
        if (p < P) { s = ps[p]; d = pd[p]; }
        else       { s = ns[p - P]; d = nd[p - P]; }
        sidx[tid] = s; didx[tid] = d;
    }
    __syncthreads();

    int tx = tid & 15, ty = tid >> 4;
    unsigned long long acc2[8][4];
#pragma unroll
    for (int i = 0; i < 8; i++)
#pragma unroll
        for (int j = 0; j < 4; j++) acc2[i][j] = 0ull;

    int lane16 = tid & 15, grp = tid >> 4;

    for (int k0 = 0; k0 < 256; k0 += 32) {
        // build Z chunk on the fly (hc is L2-resident: 4 MB), float2 loads
#pragma unroll
        for (int pp = 0; pp < 8; pp++) {
            int p = grp * 8 + pp;
            const float* sr = hc + (size_t)sidx[p] * DD + k0;
            const float* dr = hc + (size_t)didx[p] * DD + k0;
            float2 a = *(const float2*)&sr[lane16 * 2];
            float2 b = *(const float2*)&dr[lane16 * 2];
            float2 z; z.x = a.x * b.x; z.y = a.y * b.y;
            *(float2*)&Zs[p][lane16 * 2] = z;
        }
#pragma unroll
        for (int j = 0; j < 16; j++) {
            int idx = tid + j * 256;
            int k = idx >> 7, n = idx & 127;
            Ws[k][n] = w1t[(size_t)(k0 + k) * 128 + n];
        }
        __syncthreads();
#pragma unroll 4
        for (int k = 0; k < 32; k++) {
            ulonglong2 b0 = *(const ulonglong2*)&Ws[k][tx * 8];
            ulonglong2 b1 = *(const ulonglong2*)&Ws[k][tx * 8 + 4];
#pragma unroll
            for (int i = 0; i < 8; i++) {
                unsigned long long ad = dup2(Zs[ty * 8 + i][k]);
                fma2(acc2[i][0], ad, b0.x);
                fma2(acc2[i][1], ad, b0.y);
                fma2(acc2[i][2], ad, b1.x);
                fma2(acc2[i][3], ad, b1.y);
            }
        }
        __syncthreads();
    }

    float pb2v = pb2[0];
#pragma unroll
    for (int i = 0; i < 8; i++) {
        float sum = 0.f;
#pragma unroll
        for (int j2 = 0; j2 < 4; j2++) {
            float h0, h1;
            upk2(acc2[i][j2], h0, h1);
            int n = tx * 8 + j2 * 2;
            float v0 = h0 + pb1[n];
            float v1 = h1 + pb1[n + 1];
            v0 = (v0 > 0.f) ? v0 : 0.2f * v0;
            v1 = (v1 > 0.f) ? v1 : 0.2f * v1;
            sum += v0 * pw2[n] + v1 * pw2[n + 1];
        }
#pragma unroll
        for (int off = 8; off; off >>= 1)
            sum += __shfl_xor_sync(0xffffffffu, sum, off, 16);
        if (tx == 0) out[p0 + ty * 8 + i] = sum + pb2v;
    }
}

// ---------------- launch ----------------
extern "C" void kernel_launch(void* const* d_in, const int* in_sizes, int n_in,
                              void* d_out, int out_size) {
    (void)in_sizes; (void)n_in; (void)out_size;
    const float* x       = (const float*)d_in[0];
    const float* edge_w  = (const float*)d_in[1];
    const int*   src     = (const int*)d_in[2];
    /* d_in[3] = dst (unused: segment-sum is over src) */
    const int* pos_src = (const int*)d_in[4];
    const int* pos_dst = (const int*)d_in[5];
    const int* neg_src = (const int*)d_in[6];
    const int* neg_dst = (const int*)d_in[7];
    const float* proj_w = (const float*)d_in[8];
    const float* proj_b = (const float*)d_in[9];
    const float* in_w   = (const float*)d_in[10];
    const float* in_b   = (const float*)d_in[11];
    const float* out_w  = (const float*)d_in[12];
    const float* out_b  = (const float*)d_in[13];
    const float* ff_w   = (const float*)d_in[14];
    const float* ff_b   = (const float*)d_in[15];
    const float* g1     = (const float*)d_in[16];
    const float* b1     = (const float*)d_in[17];
    const float* g2     = (const float*)d_in[18];
    const float* b2     = (const float*)d_in[19];
    const float* pw1    = (const float*)d_in[20];
    const float* pb1    = (const float*)d_in[21];
    const float* pw2    = (const float*)d_in[22];
    const float* pb2    = (const float*)d_in[23];

    float* out = (float*)d_out;
    float* out_hc = out + 2 * PP;   // [pos(P) | neg(P) | h_combined(N*D)]

    float *h, *hproj, *qkv, *attn, *attnout, *tmp, *ws;
    float *projT, *inT, *outT, *ffT, *pw1T;
    cudaGetSymbolAddress((void**)&h, g_h);
    cudaGetSymbolAddress((void**)&hproj, g_hproj);
    cudaGetSymbolAddress((void**)&qkv, g_qkv);
    cudaGetSymbolAddress((void**)&attn, g_attn);
    cudaGetSymbolAddress((void**)&attnout, g_attnout);
    cudaGetSymbolAddress((void**)&tmp, g_tmp);
    cudaGetSymbolAddress((void**)&ws, g_ws);
    cudaGetSymbolAddress((void**)&projT, g_projT);
    cudaGetSymbolAddress((void**)&inT, g_inT);
    cudaGetSymbolAddress((void**)&outT, g_outT);
    cudaGetSymbolAddress((void**)&ffT, g_ffT);
    cudaGetSymbolAddress((void**)&pw1T, g_pw1T);

    dim3 tb(32, 32);
    transpose_kernel<<<dim3(4, 8),  tb>>>(projT, proj_w, 256, 128);   // -> 128x256
    transpose_kernel<<<dim3(8, 4),  tb>>>(pw1T, pw1, 128, 256);       // -> 256x128
    for (int l = 0; l < LL; l++) {
        transpose_kernel<<<dim3(8, 24), tb>>>(inT + l * 256 * 768, in_w + l * 768 * 256, 768, 256);
        transpose_kernel<<<dim3(8, 8),  tb>>>(outT + l * 256 * 256, out_w + l * 256 * 256, 256, 256);
        transpose_kernel<<<dim3(8, 8),  tb>>>(ffT + l * 256 * 256, ff_w + l * 256 * 256, 256, 256);
    }

    gemm_bias<<<dim3(4, 64), 256>>>(x, projT, proj_b, hproj, NN, DD, INF_);
    copy_kernel<<<NN * DD / 256, 256>>>(h, hproj);

    for (int l = 0; l < LL; l++) {
        gemm_bias<<<dim3(12, 64), 256>>>(h, inT + l * 256 * 768, in_b + l * 768, qkv, NN, 3 * DD, DD);
        flash_kernel<<<dim3(NN / 64, HH), 256>>>(qkv, attn);
        gemm_bias<<<dim3(4, 64), 256>>>(attn, outT + l * 256 * 256, out_b + l * DD, attnout, NN, DD, DD);
        zero_kernel<<<NN / 256, 256>>>(ws);
        scatter_kernel<<<EE / 256, 256>>>(edge_w + (size_t)l * EE, src + (size_t)l * EE, ws, EE);
        ln_kernel<<<NN, 256>>>(h, attnout, ws, g1 + l * DD, b1 + l * DD);
        gemm_bias<<<dim3(4, 64), 256>>>(h, ffT + l * 256 * 256, ff_b + l * DD, tmp, NN, DD, DD);
        ln_kernel<<<NN, 256>>>(h, tmp, nullptr, g2 + l * DD, b2 + l * DD);
    }

    add2_kernel<<<NN * DD / 256, 256>>>(out_hc, h, hproj);
    predict_kernel<<<(2 * PP) / 128, 256>>>(out_hc, pos_src, pos_dst, neg_src, neg_dst,
                                            pw1T, pb1, pw2, pb2, out, PP);
}